// round 14
// baseline (speedup 1.0000x reference)
#include <cuda_runtime.h>
#include <cuda_fp16.h>
#include <cstdint>

// ---------------------------------------------------------------------------
// BigramTransformer forward — fp16 HMMA GEMMs (fp32 accum), fp16 qkv,
// fused FFN1+FFN2 kernel (mid in smem), fused-LN epilogues,
// 4-thread/row attention.  B=2048 T=64 D=128 H=4 HD=32 L=6 V=256 DFF=512
// ---------------------------------------------------------------------------

#define Bc   2048
#define Tc   64
#define Dc   128
#define Hc   4
#define HDc  32
#define Lc   6
#define Vc   256
#define DFFc 512
#define NTOK (Bc * Tc)          /* 131072 */
#define QKVC (3 * Dc)           /* 384    */

// ------------------------- scratch (device globals) ------------------------
__device__ float  g_x  [(size_t)NTOK * Dc];
__device__ __half g_qkv[(size_t)NTOK * QKVC];
__device__ __half g_hh [(size_t)NTOK * Dc];
__device__ __half g_ah [(size_t)NTOK * Dc];
// transposed fp16 weights [N,K]
__device__ __half g_wqkv[Lc * QKVC * Dc];
__device__ __half g_wo  [Lc * Dc * Dc];
__device__ __half g_w1  [Lc * DFFc * Dc];
__device__ __half g_w2  [Lc * Dc * DFFc];
__device__ __half g_whd [Vc * Dc];

// ------------------------- helpers ------------------------------------------
__device__ __forceinline__ uint32_t smem_u32(const void* p) {
    uint32_t a;
    asm("{ .reg .u64 t; cvta.to.shared.u64 t, %1; cvt.u32.u64 %0, t; }"
        : "=r"(a) : "l"(p));
    return a;
}
__device__ __forceinline__ void h2_store(float v0, float v1, __half* p) {
    *(__half2*)p = __floats2half2_rn(v0, v1);
}

#define LDMX4(r0, r1, r2, r3, a)                                            \
    asm volatile("ldmatrix.sync.aligned.m8n8.x4.shared.b16 {%0,%1,%2,%3}, [%4];" \
                 : "=r"(r0), "=r"(r1), "=r"(r2), "=r"(r3) : "r"(a))

#define MMA(d, a0, a1, a2, a3, b0v, b1v)                                    \
    asm volatile("mma.sync.aligned.m16n8k16.row.col.f32.f16.f16.f32 "       \
                 "{%0,%1,%2,%3}, {%4,%5,%6,%7}, {%8,%9}, {%0,%1,%2,%3};"    \
                 : "+f"((d)[0]), "+f"((d)[1]), "+f"((d)[2]), "+f"((d)[3])   \
                 : "r"(a0), "r"(a1), "r"(a2), "r"(a3), "r"(b0v), "r"(b1v))

#define CP_ASYNC16(dst, src)                                                \
    asm volatile("cp.async.cg.shared.global [%0], [%1], 16;"                \
                 :: "r"(dst), "l"(src))
#define CP_COMMIT() asm volatile("cp.async.commit_group;" ::: "memory")
#define CP_WAIT(n)  asm volatile("cp.async.wait_group %0;" :: "n"(n) : "memory")

// ------------------------- weight conversion --------------------------------
__global__ void convw_kernel(const float* __restrict__ W,
                             __half* __restrict__ oh, int K, int N)
{
    const size_t base = (size_t)blockIdx.y * K * N;
    int i = blockIdx.x * 256 + threadIdx.x;
    if (i >= K * N) return;
    int k = i / N, n = i % N;
    oh[base + (size_t)n * K + k] = __float2half(W[base + i]);
}

__global__ void convqkv_kernel(const float* __restrict__ Wq,
                               const float* __restrict__ Wk,
                               const float* __restrict__ Wv,
                               __half* __restrict__ oh)
{
    int i = blockIdx.x * 256 + threadIdx.x;
    const int total = Lc * Hc * Dc * HDc;
    if (i >= total) return;
    int e = i % HDc;
    int d = (i / HDc) % Dc;
    int h = (i / (HDc * Dc)) % Hc;
    int l = i / (HDc * Dc * Hc);
    int src = ((l * Hc + h) * Dc + d) * HDc + e;
    const int col = h * HDc + e;
    oh[((size_t)l * QKVC + col) * Dc + d]          = __float2half(Wq[src]);
    oh[((size_t)l * QKVC + Dc + col) * Dc + d]     = __float2half(Wk[src]);
    oh[((size_t)l * QKVC + 2 * Dc + col) * Dc + d] = __float2half(Wv[src]);
}

// ------------------------- embedding + first LN (warp / token) --------------
__global__ __launch_bounds__(256) void embed_ln_kernel(
    const int* __restrict__ idx,
    const float* __restrict__ tok, const float* __restrict__ pos,
    float* __restrict__ xout, __half* __restrict__ oh,
    const float* __restrict__ gam, const float* __restrict__ bet)
{
    const int warp = threadIdx.x >> 5;
    const int lane = threadIdx.x & 31;
    const size_t n = (size_t)blockIdx.x * 8 + warp;
    const int t = (int)(n & (Tc - 1));
    const int v = idx[n];

    const float4 tv = ((const float4*)(tok + (size_t)v * Dc))[lane];
    const float4 pv = ((const float4*)(pos + (size_t)t * Dc))[lane];
    float4 x = make_float4(tv.x + pv.x, tv.y + pv.y, tv.z + pv.z, tv.w + pv.w);
    ((float4*)(xout + n * Dc))[lane] = x;

    float s = x.x + x.y + x.z + x.w;
    #pragma unroll
    for (int o = 16; o > 0; o >>= 1) s += __shfl_xor_sync(0xffffffffu, s, o);
    const float mean = s * (1.0f / Dc);

    float4 c = make_float4(x.x - mean, x.y - mean, x.z - mean, x.w - mean);
    float q = c.x * c.x + c.y * c.y + c.z * c.z + c.w * c.w;
    #pragma unroll
    for (int o = 16; o > 0; o >>= 1) q += __shfl_xor_sync(0xffffffffu, q, o);
    const float r = rsqrtf(q * (1.0f / Dc) + 1e-5f);

    const float4 g = ((const float4*)gam)[lane];
    const float4 b = ((const float4*)bet)[lane];
    h2_store(c.x * r * g.x + b.x, c.y * r * g.y + b.y, oh + n * Dc + lane * 4);
    h2_store(c.z * r * g.z + b.z, c.w * r * g.w + b.w, oh + n * Dc + lane * 4 + 2);
}

// ------------------------- fp16 HMMA GEMM (K-chunk 64, 2-stage pipeline) ----
#define TROWB 144
#define TILEB (128 * TROWB)
#define STAGEB (2 * TILEB)
#define HGEMM_SMEM (2 * STAGEB)

__global__ __launch_bounds__(256, 2) void hgemm_kernel(
    const __half* __restrict__ A, const __half* __restrict__ B,
    const float* __restrict__ bias, const float* __restrict__ res,
    float* __restrict__ outf, __half* __restrict__ outh,
    const float* __restrict__ lnG, const float* __restrict__ lnB,
    int M, int N, int K, int relu)
{
    extern __shared__ char smem[];
    const uint32_t sb = smem_u32(smem);

    const int tid = threadIdx.x;
    const int w   = tid >> 5;
    const int l   = tid & 31;
    const int wm  = w & 1;
    const int wn  = w >> 1;
    const int m0  = blockIdx.y * 128;
    const int n0  = blockIdx.x * 128;

    const int g    = l >> 3;
    const int idx  = l & 7;
    const int lrow = (g & 1) * 8 + idx;
    const int g2   = (g >> 1) * 16;

    const uint32_t arow = (uint32_t)(wm * 64 + lrow) * TROWB + g2;
    const uint32_t brow = (uint32_t)(wn * 32 + lrow) * TROWB + g2;

    const __half* Asrc = A + (size_t)m0 * K;
    const __half* Bsrc = B + (size_t)n0 * K;

    const int nstep = K >> 6;

    auto stage = [&](int c) {
        const int ck = c << 6;
        const uint32_t base = sb + (uint32_t)(c & 1) * STAGEB;
        #pragma unroll
        for (int i = tid; i < 1024; i += 256) {
            const int r  = i >> 3;
            const int c8 = i & 7;
            CP_ASYNC16(base + r * TROWB + c8 * 16,
                       Asrc + (size_t)r * K + ck + c8 * 8);
        }
        #pragma unroll
        for (int i = tid; i < 1024; i += 256) {
            const int r  = i >> 3;
            const int c8 = i & 7;
            CP_ASYNC16(base + TILEB + r * TROWB + c8 * 16,
                       Bsrc + (size_t)r * K + ck + c8 * 8);
        }
        CP_COMMIT();
    };

    float acc[4][4][4] = {};

    stage(0);
    for (int c = 0; c < nstep; c++) {
        if (c + 1 < nstep) {
            stage(c + 1);
            CP_WAIT(1);
        } else {
            CP_WAIT(0);
        }
        __syncthreads();

        const uint32_t AHo = sb + (uint32_t)(c & 1) * STAGEB;
        const uint32_t BHo = AHo + TILEB;

        #pragma unroll
        for (int ks = 0; ks < 4; ks++) {
            const uint32_t kb = ks * 32;
            uint32_t bh_[2][4];
            #pragma unroll
            for (int p = 0; p < 2; p++) {
                const uint32_t bo = brow + p * (16 * TROWB) + kb;
                LDMX4(bh_[p][0], bh_[p][1], bh_[p][2], bh_[p][3], BHo + bo);
            }
            #pragma unroll
            for (int mt = 0; mt < 4; mt++) {
                const uint32_t ao = arow + mt * (16 * TROWB) + kb;
                uint32_t a0, a1, a2, a3;
                LDMX4(a0, a1, a2, a3, AHo + ao);
                #pragma unroll
                for (int nt = 0; nt < 4; nt++) {
                    const int p = nt >> 1, q = nt & 1;
                    MMA(acc[mt][nt], a0, a1, a2, a3, bh_[p][q], bh_[p][q + 2]);
                }
            }
        }
        __syncthreads();
    }

    const int gr = l >> 2;
    const int gc = (l & 3) * 2;

    if (lnG) {
        float* sums  = (float*)smem;
        float* sumsq = (float*)smem + 512;

        #pragma unroll
        for (int mt = 0; mt < 4; mt++) {
            #pragma unroll
            for (int h = 0; h < 2; h++) {
                const int r64 = wm * 64 + mt * 16 + gr + h * 8;
                const size_t row = (size_t)m0 + r64;
                float s = 0.f, q = 0.f;
                #pragma unroll
                for (int nt = 0; nt < 4; nt++) {
                    const int n = wn * 32 + nt * 8 + gc;
                    float v0 = acc[mt][nt][h * 2];
                    float v1 = acc[mt][nt][h * 2 + 1];
                    const float2 bb = *(const float2*)(bias + n);
                    v0 += bb.x; v1 += bb.y;
                    const float2 rr = *(const float2*)(res + row * Dc + n);
                    v0 += rr.x; v1 += rr.y;
                    acc[mt][nt][h * 2]     = v0;
                    acc[mt][nt][h * 2 + 1] = v1;
                    *(float2*)(outf + row * Dc + n) = make_float2(v0, v1);
                    s += v0 + v1;
                    q += v0 * v0 + v1 * v1;
                }
                s += __shfl_xor_sync(0xffffffffu, s, 1);
                s += __shfl_xor_sync(0xffffffffu, s, 2);
                q += __shfl_xor_sync(0xffffffffu, q, 1);
                q += __shfl_xor_sync(0xffffffffu, q, 2);
                if ((l & 3) == 0) {
                    sums [r64 * 4 + wn] = s;
                    sumsq[r64 * 4 + wn] = q;
                }
            }
        }
        __syncthreads();
        #pragma unroll
        for (int mt = 0; mt < 4; mt++) {
            #pragma unroll
            for (int h = 0; h < 2; h++) {
                const int r64 = wm * 64 + mt * 16 + gr + h * 8;
                const size_t row = (size_t)m0 + r64;
                float S = sums[r64 * 4] + sums[r64 * 4 + 1]
                        + sums[r64 * 4 + 2] + sums[r64 * 4 + 3];
                float Q = sumsq[r64 * 4] + sumsq[r64 * 4 + 1]
                        + sumsq[r64 * 4 + 2] + sumsq[r64 * 4 + 3];
                const float mean = S * (1.0f / Dc);
                const float var  = Q * (1.0f / Dc) - mean * mean;
                const float rst  = rsqrtf(var + 1e-5f);
                #pragma unroll
                for (int nt = 0; nt < 4; nt++) {
                    const int n = wn * 32 + nt * 8 + gc;
                    const float2 gg = *(const float2*)(lnG + n);
                    const float2 bb = *(const float2*)(lnB + n);
                    const float v0 = acc[mt][nt][h * 2];
                    const float v1 = acc[mt][nt][h * 2 + 1];
                    h2_store((v0 - mean) * rst * gg.x + bb.x,
                             (v1 - mean) * rst * gg.y + bb.y,
                             outh + row * Dc + n);
                }
            }
        }
        return;
    }

    #pragma unroll
    for (int mt = 0; mt < 4; mt++) {
        #pragma unroll
        for (int h = 0; h < 2; h++) {
            const size_t row = (size_t)m0 + wm * 64 + mt * 16 + gr + h * 8;
            #pragma unroll
            for (int nt = 0; nt < 4; nt++) {
                const int n = n0 + wn * 32 + nt * 8 + gc;
                float v0 = acc[mt][nt][h * 2];
                float v1 = acc[mt][nt][h * 2 + 1];
                if (bias) {
                    const float2 bb = *(const float2*)(bias + n);
                    v0 += bb.x; v1 += bb.y;
                }
                if (relu) { v0 = fmaxf(v0, 0.f); v1 = fmaxf(v1, 0.f); }
                if (outh) {
                    h2_store(v0, v1, outh + row * N + n);
                } else {
                    *(float2*)(outf + row * N + n) = make_float2(v0, v1);
                }
            }
        }
    }
}

// ------------------------- fused FFN: relu(h@W1+b1)@W2+b2 + res + LN --------
// One CTA = 128 tokens.  mid lives in smem (128 x 512 fp16, stride 1040B).
#define FF_MIDSTRIDE 1040
#define FF_OFF_A  (128 * FF_MIDSTRIDE)       /* 133120 */
#define FF_OFF_B  (FF_OFF_A + 2 * TILEB)     /* 169984 */
#define FFN_SMEM  (FF_OFF_B + 2 * TILEB)     /* 206848 */

__global__ __launch_bounds__(256, 1) void ffn_kernel(
    const __half* __restrict__ A,      // hh [NTOK][128]
    const __half* __restrict__ W1t,    // [512][128]
    const float* __restrict__ b1,
    const __half* __restrict__ W2t,    // [128][512]
    const float* __restrict__ b2,
    float* __restrict__ x,             // residual in/out
    __half* __restrict__ outh,         // next hh
    const float* __restrict__ lnG, const float* __restrict__ lnB)
{
    extern __shared__ char smem[];
    const uint32_t sb = smem_u32(smem);
    const int tid = threadIdx.x;
    const int w = tid >> 5, l = tid & 31;
    const int wm = w & 1, wn = w >> 1;
    const int m0 = blockIdx.x * 128;
    const int g = l >> 3, idx = l & 7;
    const int lrow = (g & 1) * 8 + idx;
    const int g2 = (g >> 1) * 16;

    const uint32_t arow  = (uint32_t)(wm * 64 + lrow) * TROWB + g2;
    const uint32_t brow  = (uint32_t)(wn * 32 + lrow) * TROWB + g2;
    const uint32_t mrowA = (uint32_t)(wm * 64 + lrow) * FF_MIDSTRIDE + g2;

    const int gr = l >> 2, gc = (l & 3) * 2;

    // stage A (hh tile, both k-chunks) — joins first commit group below
    #pragma unroll
    for (int kc = 0; kc < 2; kc++) {
        const uint32_t dst = sb + FF_OFF_A + kc * TILEB;
        #pragma unroll
        for (int i = tid; i < 1024; i += 256) {
            const int r = i >> 3, c8 = i & 7;
            CP_ASYNC16(dst + r * TROWB + c8 * 16,
                       A + (size_t)(m0 + r) * Dc + kc * 64 + c8 * 8);
        }
    }

    // ---- phase A: FFN1 in 4 n-chunks of 128 ----
    for (int nch = 0; nch < 4; nch++) {
        #pragma unroll
        for (int kc = 0; kc < 2; kc++) {
            const uint32_t dst = sb + FF_OFF_B + kc * TILEB;
            const __half* src = W1t + (size_t)(nch * 128) * Dc + kc * 64;
            #pragma unroll
            for (int i = tid; i < 1024; i += 256) {
                const int r = i >> 3, c8 = i & 7;
                CP_ASYNC16(dst + r * TROWB + c8 * 16,
                           src + (size_t)r * Dc + c8 * 8);
            }
        }
        CP_COMMIT();
        CP_WAIT(0);
        __syncthreads();

        float acc[4][4][4] = {};
        #pragma unroll
        for (int kc = 0; kc < 2; kc++) {
            const uint32_t AHo = sb + FF_OFF_A + kc * TILEB;
            const uint32_t BHo = sb + FF_OFF_B + kc * TILEB;
            #pragma unroll
            for (int ks = 0; ks < 4; ks++) {
                const uint32_t kb = ks * 32;
                uint32_t bh_[2][4];
                #pragma unroll
                for (int p = 0; p < 2; p++) {
                    const uint32_t bo = brow + p * (16 * TROWB) + kb;
                    LDMX4(bh_[p][0], bh_[p][1], bh_[p][2], bh_[p][3], BHo + bo);
                }
                #pragma unroll
                for (int mt = 0; mt < 4; mt++) {
                    const uint32_t ao = arow + mt * (16 * TROWB) + kb;
                    uint32_t a0, a1, a2, a3;
                    LDMX4(a0, a1, a2, a3, AHo + ao);
                    #pragma unroll
                    for (int nt = 0; nt < 4; nt++) {
                        const int p = nt >> 1, q = nt & 1;
                        MMA(acc[mt][nt], a0, a1, a2, a3, bh_[p][q], bh_[p][q + 2]);
                    }
                }
            }
        }

        // epilogue: bias + relu -> mid smem
        #pragma unroll
        for (int mt = 0; mt < 4; mt++) {
            #pragma unroll
            for (int h8 = 0; h8 < 2; h8++) {
                const int r64 = wm * 64 + mt * 16 + gr + h8 * 8;
                #pragma unroll
                for (int nt = 0; nt < 4; nt++) {
                    const int nloc = wn * 32 + nt * 8 + gc;
                    const int n = nch * 128 + nloc;
                    const float2 bb = *(const float2*)(b1 + n);
                    float v0 = fmaxf(acc[mt][nt][h8 * 2]     + bb.x, 0.f);
                    float v1 = fmaxf(acc[mt][nt][h8 * 2 + 1] + bb.y, 0.f);
                    *(__half2*)(smem + r64 * FF_MIDSTRIDE + n * 2) =
                        __floats2half2_rn(v0, v1);
                }
            }
        }
        __syncthreads();   // mid visible; B buffers reusable
    }

    // ---- phase B: FFN2, K=512 in 8 chunks, double-buffered W2 ----
    auto stageB2 = [&](int kc) {
        const uint32_t dst = sb + FF_OFF_B + (uint32_t)(kc & 1) * TILEB;
        const __half* src = W2t + kc * 64;
        #pragma unroll
        for (int i = tid; i < 1024; i += 256) {
            const int r = i >> 3, c8 = i & 7;
            CP_ASYNC16(dst + r * TROWB + c8 * 16,
                       src + (size_t)r * DFFc + c8 * 8);
        }
        CP_COMMIT();
    };

    float acc[4][4][4] = {};
    stageB2(0);
    for (int kc = 0; kc < 8; kc++) {
        if (kc < 7) { stageB2(kc + 1); CP_WAIT(1); } else { CP_WAIT(0); }
        __syncthreads();
        const uint32_t BHo = sb + FF_OFF_B + (uint32_t)(kc & 1) * TILEB;
        #pragma unroll
        for (int ks = 0; ks < 4; ks++) {
            const uint32_t kb = ks * 32;
            uint32_t bh_[2][4];
            #pragma unroll
            for (int p = 0; p < 2; p++) {
                const uint32_t bo = brow + p * (16 * TROWB) + kb;
                LDMX4(bh_[p][0], bh_[p][1], bh_[p][2], bh_[p][3], BHo + bo);
            }
            #pragma unroll
            for (int mt = 0; mt < 4; mt++) {
                const uint32_t ao = mrowA + mt * (16 * FF_MIDSTRIDE)
                                  + kc * 128 + kb;
                uint32_t a0, a1, a2, a3;
                LDMX4(a0, a1, a2, a3, sb + ao);
                #pragma unroll
                for (int nt = 0; nt < 4; nt++) {
                    const int p = nt >> 1, q = nt & 1;
                    MMA(acc[mt][nt], a0, a1, a2, a3, bh_[p][q], bh_[p][q + 2]);
                }
            }
        }
        __syncthreads();
    }

    // ---- fused epilogue: bias + residual + LN (mid/stage smem now dead) ----
    float* sums  = (float*)smem;
    float* sumsq = (float*)smem + 512;

    #pragma unroll
    for (int mt = 0; mt < 4; mt++) {
        #pragma unroll
        for (int h8 = 0; h8 < 2; h8++) {
            const int r64 = wm * 64 + mt * 16 + gr + h8 * 8;
            const size_t row = (size_t)m0 + r64;
            float s = 0.f, q = 0.f;
            #pragma unroll
            for (int nt = 0; nt < 4; nt++) {
                const int n = wn * 32 + nt * 8 + gc;
                float v0 = acc[mt][nt][h8 * 2];
                float v1 = acc[mt][nt][h8 * 2 + 1];
                const float2 bb = *(const float2*)(b2 + n);
                v0 += bb.x; v1 += bb.y;
                const float2 rr = *(const float2*)(x + row * Dc + n);
                v0 += rr.x; v1 += rr.y;
                acc[mt][nt][h8 * 2]     = v0;
                acc[mt][nt][h8 * 2 + 1] = v1;
                *(float2*)(x + row * Dc + n) = make_float2(v0, v1);
                s += v0 + v1;
                q += v0 * v0 + v1 * v1;
            }
            s += __shfl_xor_sync(0xffffffffu, s, 1);
            s += __shfl_xor_sync(0xffffffffu, s, 2);
            q += __shfl_xor_sync(0xffffffffu, q, 1);
            q += __shfl_xor_sync(0xffffffffu, q, 2);
            if ((l & 3) == 0) {
                sums [r64 * 4 + wn] = s;
                sumsq[r64 * 4 + wn] = q;
            }
        }
    }
    __syncthreads();
    #pragma unroll
    for (int mt = 0; mt < 4; mt++) {
        #pragma unroll
        for (int h8 = 0; h8 < 2; h8++) {
            const int r64 = wm * 64 + mt * 16 + gr + h8 * 8;
            const size_t row = (size_t)m0 + r64;
            float S = sums[r64 * 4] + sums[r64 * 4 + 1]
                    + sums[r64 * 4 + 2] + sums[r64 * 4 + 3];
            float Q = sumsq[r64 * 4] + sumsq[r64 * 4 + 1]
                    + sumsq[r64 * 4 + 2] + sumsq[r64 * 4 + 3];
            const float mean = S * (1.0f / Dc);
            const float var  = Q * (1.0f / Dc) - mean * mean;
            const float rst  = rsqrtf(var + 1e-5f);
            #pragma unroll
            for (int nt = 0; nt < 4; nt++) {
                const int n = wn * 32 + nt * 8 + gc;
                const float2 gg = *(const float2*)(lnG + n);
                const float2 bb = *(const float2*)(lnB + n);
                const float v0 = acc[mt][nt][h8 * 2];
                const float v1 = acc[mt][nt][h8 * 2 + 1];
                h2_store((v0 - mean) * rst * gg.x + bb.x,
                         (v1 - mean) * rst * gg.y + bb.y,
                         outh + row * Dc + n);
            }
        }
    }
}

// ------------------------- attention: 4 threads per row, fp16 qkv -----------
#define QKP 36
#define WMP 68
__global__ __launch_bounds__(256) void attn_kernel(const __half* __restrict__ qkv,
                                                   __half* __restrict__ oh)
{
    __shared__ float qs[Tc][QKP];
    __shared__ float ks[Tc][QKP];
    __shared__ float vs[Tc][QKP];
    __shared__ float wm[Tc][WMP];

    const int bh  = blockIdx.x;
    const int b   = bh >> 2;
    const int h   = bh & 3;
    const int tid = threadIdx.x;

    // load q,k,v (fp16 -> fp32 smem): 3 mats x 64 rows x 4 uint4 (8 halves)
    for (int i = tid; i < 768; i += 256) {
        const int mat = i >> 8;
        const int r   = (i >> 2) & 63;
        const int j   = i & 3;
        const uint4 v = *(const uint4*)(qkv + ((size_t)(b * Tc + r)) * QKVC
                                        + mat * Dc + h * HDc + j * 8);
        const __half2* hp = (const __half2*)&v;
        float* dst = (mat == 0) ? &qs[r][8 * j] : (mat == 1) ? &ks[r][8 * j]
                                                             : &vs[r][8 * j];
        const float2 f0 = __half22float2(hp[0]);
        const float2 f1 = __half22float2(hp[1]);
        const float2 f2 = __half22float2(hp[2]);
        const float2 f3 = __half22float2(hp[3]);
        dst[0] = f0.x; dst[1] = f0.y; dst[2] = f1.x; dst[3] = f1.y;
        dst[4] = f2.x; dst[5] = f2.y; dst[6] = f3.x; dst[7] = f3.y;
    }
    __syncthreads();

    const int row = tid >> 2;
    const int sub = tid & 3;
    const float scale = 0.17677669529663687f;

    float qr[HDc];
    #pragma unroll
    for (int j = 0; j < HDc; j += 4) {
        const float4 f = *(const float4*)&qs[row][j];
        qr[j] = f.x; qr[j + 1] = f.y; qr[j + 2] = f.z; qr[j + 3] = f.w;
    }

    float wv[16];
    float mx = -1e30f;
    #pragma unroll
    for (int i = 0; i < 16; i++) {
        const int s = sub + 4 * i;
        float d = 0.f;
        #pragma unroll
        for (int j = 0; j < HDc; j += 4) {
            const float4 f = *(const float4*)&ks[s][j];
            d = fmaf(qr[j],     f.x, d);
            d = fmaf(qr[j + 1], f.y, d);
            d = fmaf(qr[j + 2], f.z, d);
            d = fmaf(qr[j + 3], f.w, d);
        }
        d *= scale;
        wv[i] = d;
        if (s <= row) mx = fmaxf(mx, d);
    }
    mx = fmaxf(mx, __shfl_xor_sync(0xffffffffu, mx, 1));
    mx = fmaxf(mx, __shfl_xor_sync(0xffffffffu, mx, 2));

    float sum = 0.f;
    #pragma unroll
    for (int i = 0; i < 16; i++) {
        const int s = sub + 4 * i;
        const float e = (s <= row) ? __expf(wv[i] - mx) : 0.f;
        wv[i] = e;
        sum += e;
    }
    sum += __shfl_xor_sync(0xffffffffu, sum, 1);
    sum += __shfl_xor_sync(0xffffffffu, sum, 2);
    const float inv = 1.f / sum;

    #pragma unroll
    for (int i = 0; i < 16; i++)
        wm[row][sub + 4 * i] = wv[i] * inv;
    __syncthreads();

    const int d0 = sub * 8;
    float acc[8] = {};
    for (int s = 0; s <= row; s++) {
        const float wgt = wm[row][s];
        const float4 v0 = *(const float4*)&vs[s][d0];
        const float4 v1 = *(const float4*)&vs[s][d0 + 4];
        acc[0] = fmaf(wgt, v0.x, acc[0]);
        acc[1] = fmaf(wgt, v0.y, acc[1]);
        acc[2] = fmaf(wgt, v0.z, acc[2]);
        acc[3] = fmaf(wgt, v0.w, acc[3]);
        acc[4] = fmaf(wgt, v1.x, acc[4]);
        acc[5] = fmaf(wgt, v1.y, acc[5]);
        acc[6] = fmaf(wgt, v1.z, acc[6]);
        acc[7] = fmaf(wgt, v1.w, acc[7]);
    }

    const size_t base = ((size_t)(b * Tc + row)) * Dc + h * HDc + d0;
    #pragma unroll
    for (int j = 0; j < 8; j += 2)
        h2_store(acc[j], acc[j + 1], oh + base + j);
}

// ------------------------- launcher -----------------------------------------
extern "C" void kernel_launch(void* const* d_in, const int* in_sizes, int n_in,
                              void* d_out, int out_size)
{
    (void)in_sizes; (void)n_in; (void)out_size;
    const int*   idx  = (const int*)  d_in[0];
    const float* tok  = (const float*)d_in[1];
    const float* pos  = (const float*)d_in[2];
    const float* Wq   = (const float*)d_in[3];
    const float* Wk   = (const float*)d_in[4];
    const float* Wv   = (const float*)d_in[5];
    const float* Wo   = (const float*)d_in[6];
    const float* bo   = (const float*)d_in[7];
    const float* ln1g = (const float*)d_in[8];
    const float* ln1b = (const float*)d_in[9];
    const float* W1   = (const float*)d_in[10];
    const float* b1   = (const float*)d_in[11];
    const float* W2   = (const float*)d_in[12];
    const float* b2   = (const float*)d_in[13];
    const float* ln2g = (const float*)d_in[14];
    const float* ln2b = (const float*)d_in[15];
    const float* lnfg = (const float*)d_in[16];
    const float* lnfb = (const float*)d_in[17];
    const float* Wh   = (const float*)d_in[18];
    const float* bhd  = (const float*)d_in[19];
    float* out = (float*)d_out;

    float *x;
    __half *qkvh, *hh, *ah, *wq, *wo, *w1, *w2, *whd;
    cudaGetSymbolAddress((void**)&x,    g_x);
    cudaGetSymbolAddress((void**)&qkvh, g_qkv);
    cudaGetSymbolAddress((void**)&hh,   g_hh);
    cudaGetSymbolAddress((void**)&ah,   g_ah);
    cudaGetSymbolAddress((void**)&wq,   g_wqkv);
    cudaGetSymbolAddress((void**)&wo,   g_wo);
    cudaGetSymbolAddress((void**)&w1,   g_w1);
    cudaGetSymbolAddress((void**)&w2,   g_w2);
    cudaGetSymbolAddress((void**)&whd,  g_whd);

    cudaFuncSetAttribute(hgemm_kernel,
                         cudaFuncAttributeMaxDynamicSharedMemorySize, HGEMM_SMEM);
    cudaFuncSetAttribute(ffn_kernel,
                         cudaFuncAttributeMaxDynamicSharedMemorySize, FFN_SMEM);

    // weight conversion
    convqkv_kernel<<<(Lc * Hc * Dc * HDc + 255) / 256, 256>>>(Wq, Wk, Wv, wq);
    convw_kernel<<<dim3((Dc * Dc + 255) / 256, Lc), 256>>>(Wo, wo, Dc, Dc);
    convw_kernel<<<dim3((Dc * DFFc + 255) / 256, Lc), 256>>>(W1, w1, Dc, DFFc);
    convw_kernel<<<dim3((DFFc * Dc + 255) / 256, Lc), 256>>>(W2, w2, DFFc, Dc);
    convw_kernel<<<dim3((Dc * Vc + 255) / 256, 1), 256>>>(Wh, whd, Dc, Vc);

    // embed + ln1 of layer 0
    embed_ln_kernel<<<NTOK / 8, 256>>>(idx, tok, pos, x, hh, ln1g, ln1b);

    const int MT = NTOK / 128;
    const dim3 gQKV(QKVC / 128, MT);
    const dim3 gD  (1,          MT);
    const dim3 gV  (Vc   / 128, MT);

    for (int l = 0; l < Lc; l++) {
        hgemm_kernel<<<gQKV, 256, HGEMM_SMEM>>>(
            hh, wq + (size_t)l * QKVC * Dc,
            nullptr, nullptr, nullptr, qkvh, nullptr, nullptr,
            NTOK, QKVC, Dc, 0);
        attn_kernel<<<Bc * Hc, 256>>>(qkvh, ah);
        hgemm_kernel<<<gD, 256, HGEMM_SMEM>>>(
            ah, wo + (size_t)l * Dc * Dc,
            bo + l * Dc, x, x, hh, ln2g + l * Dc, ln2b + l * Dc,
            NTOK, Dc, Dc, 0);
        const float* ng = (l < Lc - 1) ? (ln1g + (l + 1) * Dc) : lnfg;
        const float* nb = (l < Lc - 1) ? (ln1b + (l + 1) * Dc) : lnfb;
        ffn_kernel<<<MT, 256, FFN_SMEM>>>(
            hh, w1 + (size_t)l * DFFc * Dc, b1 + l * DFFc,
            w2 + (size_t)l * Dc * DFFc, b2 + l * Dc,
            x, hh, ng, nb);
    }

    hgemm_kernel<<<gV, 256, HGEMM_SMEM>>>(
        hh, whd, bhd, nullptr, out, nullptr, nullptr, nullptr,
        NTOK, Vc, Dc, 0);
}

// round 15
// speedup vs baseline: 1.0183x; 1.0183x over previous
#include <cuda_runtime.h>
#include <cuda_fp16.h>
#include <cstdint>

// ---------------------------------------------------------------------------
// BigramTransformer forward — fp16 HMMA GEMMs (fp32 accum), fp16 qkv,
// separate pipelined FFN GEMMs, fused-LN epilogues, 4-thread/row attention.
// B=2048 T=64 D=128 H=4 HD=32 L=6 V=256 DFF=512
// ---------------------------------------------------------------------------

#define Bc   2048
#define Tc   64
#define Dc   128
#define Hc   4
#define HDc  32
#define Lc   6
#define Vc   256
#define DFFc 512
#define NTOK (Bc * Tc)          /* 131072 */
#define QKVC (3 * Dc)           /* 384    */

// ------------------------- scratch (device globals) ------------------------
__device__ float  g_x  [(size_t)NTOK * Dc];
__device__ __half g_qkv[(size_t)NTOK * QKVC];
__device__ __half g_hh [(size_t)NTOK * Dc];
__device__ __half g_ah [(size_t)NTOK * Dc];
__device__ __half g_mh [(size_t)NTOK * DFFc];
// transposed fp16 weights [N,K]
__device__ __half g_wqkv[Lc * QKVC * Dc];
__device__ __half g_wo  [Lc * Dc * Dc];
__device__ __half g_w1  [Lc * DFFc * Dc];
__device__ __half g_w2  [Lc * Dc * DFFc];
__device__ __half g_whd [Vc * Dc];

// ------------------------- helpers ------------------------------------------
__device__ __forceinline__ uint32_t smem_u32(const void* p) {
    uint32_t a;
    asm("{ .reg .u64 t; cvta.to.shared.u64 t, %1; cvt.u32.u64 %0, t; }"
        : "=r"(a) : "l"(p));
    return a;
}
__device__ __forceinline__ void h2_store(float v0, float v1, __half* p) {
    *(__half2*)p = __floats2half2_rn(v0, v1);
}

#define LDMX4(r0, r1, r2, r3, a)                                            \
    asm volatile("ldmatrix.sync.aligned.m8n8.x4.shared.b16 {%0,%1,%2,%3}, [%4];" \
                 : "=r"(r0), "=r"(r1), "=r"(r2), "=r"(r3) : "r"(a))

#define MMA(d, a0, a1, a2, a3, b0v, b1v)                                    \
    asm volatile("mma.sync.aligned.m16n8k16.row.col.f32.f16.f16.f32 "       \
                 "{%0,%1,%2,%3}, {%4,%5,%6,%7}, {%8,%9}, {%0,%1,%2,%3};"    \
                 : "+f"((d)[0]), "+f"((d)[1]), "+f"((d)[2]), "+f"((d)[3])   \
                 : "r"(a0), "r"(a1), "r"(a2), "r"(a3), "r"(b0v), "r"(b1v))

#define CP_ASYNC16(dst, src)                                                \
    asm volatile("cp.async.cg.shared.global [%0], [%1], 16;"                \
                 :: "r"(dst), "l"(src))
#define CP_COMMIT() asm volatile("cp.async.commit_group;" ::: "memory")
#define CP_WAIT(n)  asm volatile("cp.async.wait_group %0;" :: "n"(n) : "memory")

// ------------------------- weight conversion --------------------------------
__global__ void convw_kernel(const float* __restrict__ W,
                             __half* __restrict__ oh, int K, int N)
{
    const size_t base = (size_t)blockIdx.y * K * N;
    int i = blockIdx.x * 256 + threadIdx.x;
    if (i >= K * N) return;
    int k = i / N, n = i % N;
    oh[base + (size_t)n * K + k] = __float2half(W[base + i]);
}

__global__ void convqkv_kernel(const float* __restrict__ Wq,
                               const float* __restrict__ Wk,
                               const float* __restrict__ Wv,
                               __half* __restrict__ oh)
{
    int i = blockIdx.x * 256 + threadIdx.x;
    const int total = Lc * Hc * Dc * HDc;
    if (i >= total) return;
    int e = i % HDc;
    int d = (i / HDc) % Dc;
    int h = (i / (HDc * Dc)) % Hc;
    int l = i / (HDc * Dc * Hc);
    int src = ((l * Hc + h) * Dc + d) * HDc + e;
    const int col = h * HDc + e;
    oh[((size_t)l * QKVC + col) * Dc + d]          = __float2half(Wq[src]);
    oh[((size_t)l * QKVC + Dc + col) * Dc + d]     = __float2half(Wk[src]);
    oh[((size_t)l * QKVC + 2 * Dc + col) * Dc + d] = __float2half(Wv[src]);
}

// ------------------------- embedding + first LN (warp / token) --------------
__global__ __launch_bounds__(256) void embed_ln_kernel(
    const int* __restrict__ idx,
    const float* __restrict__ tok, const float* __restrict__ pos,
    float* __restrict__ xout, __half* __restrict__ oh,
    const float* __restrict__ gam, const float* __restrict__ bet)
{
    const int warp = threadIdx.x >> 5;
    const int lane = threadIdx.x & 31;
    const size_t n = (size_t)blockIdx.x * 8 + warp;
    const int t = (int)(n & (Tc - 1));
    const int v = idx[n];

    const float4 tv = ((const float4*)(tok + (size_t)v * Dc))[lane];
    const float4 pv = ((const float4*)(pos + (size_t)t * Dc))[lane];
    float4 x = make_float4(tv.x + pv.x, tv.y + pv.y, tv.z + pv.z, tv.w + pv.w);
    ((float4*)(xout + n * Dc))[lane] = x;

    float s = x.x + x.y + x.z + x.w;
    #pragma unroll
    for (int o = 16; o > 0; o >>= 1) s += __shfl_xor_sync(0xffffffffu, s, o);
    const float mean = s * (1.0f / Dc);

    float4 c = make_float4(x.x - mean, x.y - mean, x.z - mean, x.w - mean);
    float q = c.x * c.x + c.y * c.y + c.z * c.z + c.w * c.w;
    #pragma unroll
    for (int o = 16; o > 0; o >>= 1) q += __shfl_xor_sync(0xffffffffu, q, o);
    const float r = rsqrtf(q * (1.0f / Dc) + 1e-5f);

    const float4 g = ((const float4*)gam)[lane];
    const float4 b = ((const float4*)bet)[lane];
    h2_store(c.x * r * g.x + b.x, c.y * r * g.y + b.y, oh + n * Dc + lane * 4);
    h2_store(c.z * r * g.z + b.z, c.w * r * g.w + b.w, oh + n * Dc + lane * 4 + 2);
}

// ------------------------- fp16 HMMA GEMM (K-chunk 64, 2-stage pipeline) ----
// C[M,N] = A@B^T (+bias)(relu)(+res)
// A: [M,K] fp16 row-major; B: [N,K] fp16 row-major.
// lnG!=null (requires N==128, gridDim.x==1): write C to outf and LN(C) to outh.
#define TROWB 144
#define TILEB (128 * TROWB)
#define STAGEB (2 * TILEB)
#define HGEMM_SMEM (2 * STAGEB)

__global__ __launch_bounds__(256, 2) void hgemm_kernel(
    const __half* __restrict__ A, const __half* __restrict__ B,
    const float* __restrict__ bias, const float* __restrict__ res,
    float* __restrict__ outf, __half* __restrict__ outh,
    const float* __restrict__ lnG, const float* __restrict__ lnB,
    int M, int N, int K, int relu)
{
    extern __shared__ char smem[];
    const uint32_t sb = smem_u32(smem);

    const int tid = threadIdx.x;
    const int w   = tid >> 5;
    const int l   = tid & 31;
    const int wm  = w & 1;
    const int wn  = w >> 1;
    const int m0  = blockIdx.y * 128;
    const int n0  = blockIdx.x * 128;

    const int g    = l >> 3;
    const int idx  = l & 7;
    const int lrow = (g & 1) * 8 + idx;
    const int g2   = (g >> 1) * 16;

    const uint32_t arow = (uint32_t)(wm * 64 + lrow) * TROWB + g2;
    const uint32_t brow = (uint32_t)(wn * 32 + lrow) * TROWB + g2;

    const __half* Asrc = A + (size_t)m0 * K;
    const __half* Bsrc = B + (size_t)n0 * K;

    const int nstep = K >> 6;

    auto stage = [&](int c) {
        const int ck = c << 6;
        const uint32_t base = sb + (uint32_t)(c & 1) * STAGEB;
        #pragma unroll
        for (int i = tid; i < 1024; i += 256) {
            const int r  = i >> 3;
            const int c8 = i & 7;
            CP_ASYNC16(base + r * TROWB + c8 * 16,
                       Asrc + (size_t)r * K + ck + c8 * 8);
        }
        #pragma unroll
        for (int i = tid; i < 1024; i += 256) {
            const int r  = i >> 3;
            const int c8 = i & 7;
            CP_ASYNC16(base + TILEB + r * TROWB + c8 * 16,
                       Bsrc + (size_t)r * K + ck + c8 * 8);
        }
        CP_COMMIT();
    };

    float acc[4][4][4] = {};

    stage(0);
    for (int c = 0; c < nstep; c++) {
        if (c + 1 < nstep) {
            stage(c + 1);
            CP_WAIT(1);
        } else {
            CP_WAIT(0);
        }
        __syncthreads();

        const uint32_t AHo = sb + (uint32_t)(c & 1) * STAGEB;
        const uint32_t BHo = AHo + TILEB;

        #pragma unroll
        for (int ks = 0; ks < 4; ks++) {
            const uint32_t kb = ks * 32;
            uint32_t bh_[2][4];
            #pragma unroll
            for (int p = 0; p < 2; p++) {
                const uint32_t bo = brow + p * (16 * TROWB) + kb;
                LDMX4(bh_[p][0], bh_[p][1], bh_[p][2], bh_[p][3], BHo + bo);
            }
            #pragma unroll
            for (int mt = 0; mt < 4; mt++) {
                const uint32_t ao = arow + mt * (16 * TROWB) + kb;
                uint32_t a0, a1, a2, a3;
                LDMX4(a0, a1, a2, a3, AHo + ao);
                #pragma unroll
                for (int nt = 0; nt < 4; nt++) {
                    const int p = nt >> 1, q = nt & 1;
                    MMA(acc[mt][nt], a0, a1, a2, a3, bh_[p][q], bh_[p][q + 2]);
                }
            }
        }
        __syncthreads();
    }

    const int gr = l >> 2;
    const int gc = (l & 3) * 2;

    if (lnG) {
        // ---- fused epilogue: bias + residual + LN over the 128-wide row ----
        float* sums  = (float*)smem;
        float* sumsq = (float*)smem + 512;

        #pragma unroll
        for (int mt = 0; mt < 4; mt++) {
            #pragma unroll
            for (int h = 0; h < 2; h++) {
                const int r64 = wm * 64 + mt * 16 + gr + h * 8;
                const size_t row = (size_t)m0 + r64;
                float s = 0.f, q = 0.f;
                #pragma unroll
                for (int nt = 0; nt < 4; nt++) {
                    const int n = wn * 32 + nt * 8 + gc;
                    float v0 = acc[mt][nt][h * 2];
                    float v1 = acc[mt][nt][h * 2 + 1];
                    const float2 bb = *(const float2*)(bias + n);
                    v0 += bb.x; v1 += bb.y;
                    const float2 rr = *(const float2*)(res + row * Dc + n);
                    v0 += rr.x; v1 += rr.y;
                    acc[mt][nt][h * 2]     = v0;
                    acc[mt][nt][h * 2 + 1] = v1;
                    *(float2*)(outf + row * Dc + n) = make_float2(v0, v1);
                    s += v0 + v1;
                    q += v0 * v0 + v1 * v1;
                }
                s += __shfl_xor_sync(0xffffffffu, s, 1);
                s += __shfl_xor_sync(0xffffffffu, s, 2);
                q += __shfl_xor_sync(0xffffffffu, q, 1);
                q += __shfl_xor_sync(0xffffffffu, q, 2);
                if ((l & 3) == 0) {
                    sums [r64 * 4 + wn] = s;
                    sumsq[r64 * 4 + wn] = q;
                }
            }
        }
        __syncthreads();
        #pragma unroll
        for (int mt = 0; mt < 4; mt++) {
            #pragma unroll
            for (int h = 0; h < 2; h++) {
                const int r64 = wm * 64 + mt * 16 + gr + h * 8;
                const size_t row = (size_t)m0 + r64;
                float S = sums[r64 * 4] + sums[r64 * 4 + 1]
                        + sums[r64 * 4 + 2] + sums[r64 * 4 + 3];
                float Q = sumsq[r64 * 4] + sumsq[r64 * 4 + 1]
                        + sumsq[r64 * 4 + 2] + sumsq[r64 * 4 + 3];
                const float mean = S * (1.0f / Dc);
                const float var  = Q * (1.0f / Dc) - mean * mean;
                const float rst  = rsqrtf(var + 1e-5f);
                #pragma unroll
                for (int nt = 0; nt < 4; nt++) {
                    const int n = wn * 32 + nt * 8 + gc;
                    const float2 gg = *(const float2*)(lnG + n);
                    const float2 bb = *(const float2*)(lnB + n);
                    const float v0 = acc[mt][nt][h * 2];
                    const float v1 = acc[mt][nt][h * 2 + 1];
                    h2_store((v0 - mean) * rst * gg.x + bb.x,
                             (v1 - mean) * rst * gg.y + bb.y,
                             outh + row * Dc + n);
                }
            }
        }
        return;
    }

    // ---- plain epilogue ----
    #pragma unroll
    for (int mt = 0; mt < 4; mt++) {
        #pragma unroll
        for (int h = 0; h < 2; h++) {
            const size_t row = (size_t)m0 + wm * 64 + mt * 16 + gr + h * 8;
            #pragma unroll
            for (int nt = 0; nt < 4; nt++) {
                const int n = n0 + wn * 32 + nt * 8 + gc;
                float v0 = acc[mt][nt][h * 2];
                float v1 = acc[mt][nt][h * 2 + 1];
                if (bias) {
                    const float2 bb = *(const float2*)(bias + n);
                    v0 += bb.x; v1 += bb.y;
                }
                if (relu) { v0 = fmaxf(v0, 0.f); v1 = fmaxf(v1, 0.f); }
                if (outh) {
                    h2_store(v0, v1, outh + row * N + n);
                } else {
                    *(float2*)(outf + row * N + n) = make_float2(v0, v1);
                }
            }
        }
    }
}

// ------------------------- attention: 4 threads per row, fp16 qkv -----------
#define QKP 36
#define WMP 68
__global__ __launch_bounds__(256) void attn_kernel(const __half* __restrict__ qkv,
                                                   __half* __restrict__ oh)
{
    __shared__ float qs[Tc][QKP];
    __shared__ float ks[Tc][QKP];
    __shared__ float vs[Tc][QKP];
    __shared__ float wm[Tc][WMP];

    const int bh  = blockIdx.x;
    const int b   = bh >> 2;
    const int h   = bh & 3;
    const int tid = threadIdx.x;

    // load q,k,v (fp16 -> fp32 smem): 3 mats x 64 rows x 4 uint4 (8 halves)
    for (int i = tid; i < 768; i += 256) {
        const int mat = i >> 8;
        const int r   = (i >> 2) & 63;
        const int j   = i & 3;
        const uint4 v = *(const uint4*)(qkv + ((size_t)(b * Tc + r)) * QKVC
                                        + mat * Dc + h * HDc + j * 8);
        const __half2* hp = (const __half2*)&v;
        float* dst = (mat == 0) ? &qs[r][8 * j] : (mat == 1) ? &ks[r][8 * j]
                                                             : &vs[r][8 * j];
        const float2 f0 = __half22float2(hp[0]);
        const float2 f1 = __half22float2(hp[1]);
        const float2 f2 = __half22float2(hp[2]);
        const float2 f3 = __half22float2(hp[3]);
        dst[0] = f0.x; dst[1] = f0.y; dst[2] = f1.x; dst[3] = f1.y;
        dst[4] = f2.x; dst[5] = f2.y; dst[6] = f3.x; dst[7] = f3.y;
    }
    __syncthreads();

    const int row = tid >> 2;
    const int sub = tid & 3;
    const float scale = 0.17677669529663687f;

    float qr[HDc];
    #pragma unroll
    for (int j = 0; j < HDc; j += 4) {
        const float4 f = *(const float4*)&qs[row][j];
        qr[j] = f.x; qr[j + 1] = f.y; qr[j + 2] = f.z; qr[j + 3] = f.w;
    }

    float wv[16];
    float mx = -1e30f;
    #pragma unroll
    for (int i = 0; i < 16; i++) {
        const int s = sub + 4 * i;
        float d = 0.f;
        #pragma unroll
        for (int j = 0; j < HDc; j += 4) {
            const float4 f = *(const float4*)&ks[s][j];
            d = fmaf(qr[j],     f.x, d);
            d = fmaf(qr[j + 1], f.y, d);
            d = fmaf(qr[j + 2], f.z, d);
            d = fmaf(qr[j + 3], f.w, d);
        }
        d *= scale;
        wv[i] = d;
        if (s <= row) mx = fmaxf(mx, d);
    }
    mx = fmaxf(mx, __shfl_xor_sync(0xffffffffu, mx, 1));
    mx = fmaxf(mx, __shfl_xor_sync(0xffffffffu, mx, 2));

    float sum = 0.f;
    #pragma unroll
    for (int i = 0; i < 16; i++) {
        const int s = sub + 4 * i;
        const float e = (s <= row) ? __expf(wv[i] - mx) : 0.f;
        wv[i] = e;
        sum += e;
    }
    sum += __shfl_xor_sync(0xffffffffu, sum, 1);
    sum += __shfl_xor_sync(0xffffffffu, sum, 2);
    const float inv = 1.f / sum;

    #pragma unroll
    for (int i = 0; i < 16; i++)
        wm[row][sub + 4 * i] = wv[i] * inv;
    __syncthreads();

    const int d0 = sub * 8;
    float acc[8] = {};
    for (int s = 0; s <= row; s++) {
        const float wgt = wm[row][s];
        const float4 v0 = *(const float4*)&vs[s][d0];
        const float4 v1 = *(const float4*)&vs[s][d0 + 4];
        acc[0] = fmaf(wgt, v0.x, acc[0]);
        acc[1] = fmaf(wgt, v0.y, acc[1]);
        acc[2] = fmaf(wgt, v0.z, acc[2]);
        acc[3] = fmaf(wgt, v0.w, acc[3]);
        acc[4] = fmaf(wgt, v1.x, acc[4]);
        acc[5] = fmaf(wgt, v1.y, acc[5]);
        acc[6] = fmaf(wgt, v1.z, acc[6]);
        acc[7] = fmaf(wgt, v1.w, acc[7]);
    }

    const size_t base = ((size_t)(b * Tc + row)) * Dc + h * HDc + d0;
    #pragma unroll
    for (int j = 0; j < 8; j += 2)
        h2_store(acc[j], acc[j + 1], oh + base + j);
}

// ------------------------- launcher -----------------------------------------
extern "C" void kernel_launch(void* const* d_in, const int* in_sizes, int n_in,
                              void* d_out, int out_size)
{
    (void)in_sizes; (void)n_in; (void)out_size;
    const int*   idx  = (const int*)  d_in[0];
    const float* tok  = (const float*)d_in[1];
    const float* pos  = (const float*)d_in[2];
    const float* Wq   = (const float*)d_in[3];
    const float* Wk   = (const float*)d_in[4];
    const float* Wv   = (const float*)d_in[5];
    const float* Wo   = (const float*)d_in[6];
    const float* bo   = (const float*)d_in[7];
    const float* ln1g = (const float*)d_in[8];
    const float* ln1b = (const float*)d_in[9];
    const float* W1   = (const float*)d_in[10];
    const float* b1   = (const float*)d_in[11];
    const float* W2   = (const float*)d_in[12];
    const float* b2   = (const float*)d_in[13];
    const float* ln2g = (const float*)d_in[14];
    const float* ln2b = (const float*)d_in[15];
    const float* lnfg = (const float*)d_in[16];
    const float* lnfb = (const float*)d_in[17];
    const float* Wh   = (const float*)d_in[18];
    const float* bhd  = (const float*)d_in[19];
    float* out = (float*)d_out;

    float *x;
    __half *qkvh, *hh, *ah, *mh, *wq, *wo, *w1, *w2, *whd;
    cudaGetSymbolAddress((void**)&x,    g_x);
    cudaGetSymbolAddress((void**)&qkvh, g_qkv);
    cudaGetSymbolAddress((void**)&hh,   g_hh);
    cudaGetSymbolAddress((void**)&ah,   g_ah);
    cudaGetSymbolAddress((void**)&mh,   g_mh);
    cudaGetSymbolAddress((void**)&wq,   g_wqkv);
    cudaGetSymbolAddress((void**)&wo,   g_wo);
    cudaGetSymbolAddress((void**)&w1,   g_w1);
    cudaGetSymbolAddress((void**)&w2,   g_w2);
    cudaGetSymbolAddress((void**)&whd,  g_whd);

    cudaFuncSetAttribute(hgemm_kernel,
                         cudaFuncAttributeMaxDynamicSharedMemorySize, HGEMM_SMEM);

    // weight conversion
    convqkv_kernel<<<(Lc * Hc * Dc * HDc + 255) / 256, 256>>>(Wq, Wk, Wv, wq);
    convw_kernel<<<dim3((Dc * Dc + 255) / 256, Lc), 256>>>(Wo, wo, Dc, Dc);
    convw_kernel<<<dim3((Dc * DFFc + 255) / 256, Lc), 256>>>(W1, w1, Dc, DFFc);
    convw_kernel<<<dim3((DFFc * Dc + 255) / 256, Lc), 256>>>(W2, w2, DFFc, Dc);
    convw_kernel<<<dim3((Dc * Vc + 255) / 256, 1), 256>>>(Wh, whd, Dc, Vc);

    // embed + ln1 of layer 0
    embed_ln_kernel<<<NTOK / 8, 256>>>(idx, tok, pos, x, hh, ln1g, ln1b);

    const int MT = NTOK / 128;
    const dim3 gQKV(QKVC / 128, MT);
    const dim3 gD  (1,          MT);
    const dim3 gFF (DFFc / 128, MT);
    const dim3 gV  (Vc   / 128, MT);

    for (int l = 0; l < Lc; l++) {
        // QKV projection -> fp16 qkv
        hgemm_kernel<<<gQKV, 256, HGEMM_SMEM>>>(
            hh, wq + (size_t)l * QKVC * Dc,
            nullptr, nullptr, nullptr, qkvh, nullptr, nullptr,
            NTOK, QKVC, Dc, 0);
        attn_kernel<<<Bc * Hc, 256>>>(qkvh, ah);
        // Wo projection + residual + fused LN2
        hgemm_kernel<<<gD, 256, HGEMM_SMEM>>>(
            ah, wo + (size_t)l * Dc * Dc,
            bo + l * Dc, x, x, hh, ln2g + l * Dc, ln2b + l * Dc,
            NTOK, Dc, Dc, 0);
        // FFN1 + relu -> fp16 mid
        hgemm_kernel<<<gFF, 256, HGEMM_SMEM>>>(
            hh, w1 + (size_t)l * DFFc * Dc,
            b1 + l * DFFc, nullptr, nullptr, mh, nullptr, nullptr,
            NTOK, DFFc, Dc, 1);
        // FFN2 + residual + fused LN (next ln1 or lnf)
        const float* ng = (l < Lc - 1) ? (ln1g + (l + 1) * Dc) : lnfg;
        const float* nb = (l < Lc - 1) ? (ln1b + (l + 1) * Dc) : lnfb;
        hgemm_kernel<<<gD, 256, HGEMM_SMEM>>>(
            mh, w2 + (size_t)l * Dc * DFFc,
            b2 + l * Dc, x, x, hh, ng, nb,
            NTOK, Dc, DFFc, 0);
    }

    hgemm_kernel<<<gV, 256, HGEMM_SMEM>>>(
        hh, whd, bhd, nullptr, out, nullptr, nullptr, nullptr,
        NTOK, Vc, Dc, 0);
}